// round 12
// baseline (speedup 1.0000x reference)
#include <cuda_runtime.h>
#include <cuda_fp16.h>

#define N_NODES 100000
#define D 128
#define N_ADJ 6
#define NNZ 600000
#define TOTAL_E (N_ADJ * NNZ)
#define N_HOPS 7
#define CAP 128   // fixed bucket capacity per row (mean 36, sigma 6 -> overflow prob ~1e-40)

// ---------------- device scratch (static, no allocations) ----------------
__device__ int    g_count[N_NODES];
__device__ int2   g_edges[(size_t)N_NODES * CAP]; // (col, weight-as-int), bucketed per row
__device__ __half g_inph[(size_t)N_NODES * D];    // fp16 copy of input for gather
__device__ float  g_rep[(size_t)N_NODES * D];     // fallback if d_out lacks rep slot

// inline softmax of the 7 mixing weights (pure function of linw -> deterministic)
__device__ __forceinline__ float mix_weight(const float* __restrict__ lw, int i) {
    float m = lw[0];
    #pragma unroll
    for (int k = 1; k < N_HOPS; k++) m = fmaxf(m, lw[k]);
    float s = 0.f;
    #pragma unroll
    for (int k = 0; k < N_HOPS; k++) s += expf(lw[k] - m);
    return expf(lw[i] - m) / s;
}

// ---------------- prep: fp32 -> fp16 copy of input, plus zero counts ----------------
__global__ void prep_kernel(const float4* __restrict__ in) {
    int i = blockIdx.x * blockDim.x + threadIdx.x;  // over N*D/4 = 3.2M
    if (i < N_NODES) g_count[i] = 0;
    if (i < N_NODES * D / 4) {
        float4 v = in[i];
        __half2 h0 = __floats2half2_rn(v.x, v.y);
        __half2 h1 = __floats2half2_rn(v.z, v.w);
        uint2 u;
        u.x = *reinterpret_cast<unsigned*>(&h0);
        u.y = *reinterpret_cast<unsigned*>(&h1);
        reinterpret_cast<uint2*>(g_inph)[i] = u;
    }
}

// ---------------- fill: one pass, bucketed scatter of (col, mix*val) ----------------
__global__ void fill_kernel(const int* __restrict__ rows,
                            const int* __restrict__ cols,
                            const float* __restrict__ vals,
                            const float* __restrict__ lw) {
    int e = blockIdx.x * blockDim.x + threadIdx.x;
    if (e >= TOTAL_E) return;
    int a = e / NNZ;
    int r = rows[e];
    int c = cols[e];
    float w = mix_weight(lw, a + 1) * vals[e];
    int slot = atomicAdd(&g_count[r], 1);
    if (slot < CAP)
        g_edges[(size_t)r * CAP + slot] = make_int2(c, __float_as_int(w));
}

// ---------------- gather: one warp per row; neighbors from fp16, acc fp32 ----------------
__device__ __forceinline__ void gacc(float4& acc, float w, uint2 u) {
    __half2 h0 = *reinterpret_cast<__half2*>(&u.x);
    __half2 h1 = *reinterpret_cast<__half2*>(&u.y);
    float2 f0 = __half22float2(h0);
    float2 f1 = __half22float2(h1);
    acc.x = fmaf(w, f0.x, acc.x);
    acc.y = fmaf(w, f0.y, acc.y);
    acc.z = fmaf(w, f1.x, acc.z);
    acc.w = fmaf(w, f1.y, acc.w);
}

__global__ __launch_bounds__(256) void gather_kernel(const float* __restrict__ input,
                                                     const float* __restrict__ lw,
                                                     float* __restrict__ rep) {
    int gw = (blockIdx.x * blockDim.x + threadIdx.x) >> 5;  // global warp = row
    int lane = threadIdx.x & 31;
    if (gw >= N_NODES) return;
    int row = gw;

    float m0 = mix_weight(lw, 0);
    float4 acc = reinterpret_cast<const float4*>(input + (size_t)row * D)[lane];
    acc.x *= m0; acc.y *= m0; acc.z *= m0; acc.w *= m0;

    int cnt = min(g_count[row], CAP);
    const int2* eb = g_edges + (size_t)row * CAP;

    int e = 0;
    // 4x unrolled: 4 independent row-gathers in flight
    for (; e + 4 <= cnt; e += 4) {
        int2 e0 = __ldg(eb + e + 0);
        int2 e1 = __ldg(eb + e + 1);
        int2 e2 = __ldg(eb + e + 2);
        int2 e3 = __ldg(eb + e + 3);
        uint2 u0 = __ldg(reinterpret_cast<const uint2*>(g_inph + (size_t)e0.x * D) + lane);
        uint2 u1 = __ldg(reinterpret_cast<const uint2*>(g_inph + (size_t)e1.x * D) + lane);
        uint2 u2 = __ldg(reinterpret_cast<const uint2*>(g_inph + (size_t)e2.x * D) + lane);
        uint2 u3 = __ldg(reinterpret_cast<const uint2*>(g_inph + (size_t)e3.x * D) + lane);
        gacc(acc, __int_as_float(e0.y), u0);
        gacc(acc, __int_as_float(e1.y), u1);
        gacc(acc, __int_as_float(e2.y), u2);
        gacc(acc, __int_as_float(e3.y), u3);
    }
    for (; e < cnt; e++) {
        int2 ed = __ldg(eb + e);
        uint2 u = __ldg(reinterpret_cast<const uint2*>(g_inph + (size_t)ed.x * D) + lane);
        gacc(acc, __int_as_float(ed.y), u);
    }
    reinterpret_cast<float4*>(rep + (size_t)row * D)[lane] = acc;
}

// ---------------- out = rep @ W + bias  (128x128 tile, 8x8 microtile, all LDS.128) ----------------
#define GBM 128
#define GBK 16
__global__ __launch_bounds__(256) void gemm_kernel(const float* __restrict__ rep,
                                                   const float* __restrict__ W,
                                                   const float* __restrict__ bias,
                                                   float* __restrict__ out) {
    __shared__ float As[GBK][GBM + 4];
    __shared__ float Bs[GBK][D];

    int tid = threadIdx.x;
    int tx = tid & 15;   // col groups: [tx*4, tx*4+4) and [64+tx*4, ...)
    int ty = tid >> 4;   // rows [ty*8, ty*8+8)
    int rowBase = blockIdx.x * GBM;

    float acc[8][8];
    #pragma unroll
    for (int i = 0; i < 8; i++)
        #pragma unroll
        for (int j = 0; j < 8; j++) acc[i][j] = 0.f;

    for (int kk = 0; kk < D; kk += GBK) {
        // Load A tile (128 x 16): 512 float4, 2 per thread, transposed into As[k][r]
        #pragma unroll
        for (int l = 0; l < 2; l++) {
            int i = tid + l * 256;
            int r = i >> 2;
            int c4 = (i & 3) * 4;
            float4 v = make_float4(0.f, 0.f, 0.f, 0.f);
            int gr = rowBase + r;
            if (gr < N_NODES)
                v = *reinterpret_cast<const float4*>(rep + (size_t)gr * D + kk + c4);
            As[c4 + 0][r] = v.x;
            As[c4 + 1][r] = v.y;
            As[c4 + 2][r] = v.z;
            As[c4 + 3][r] = v.w;
        }
        // Load B tile (16 x 128): 512 float4, 2 per thread
        #pragma unroll
        for (int l = 0; l < 2; l++) {
            int i = tid + l * 256;
            int k = i >> 5;
            int n4 = (i & 31) * 4;
            float4 v = *reinterpret_cast<const float4*>(W + (size_t)(kk + k) * D + n4);
            *reinterpret_cast<float4*>(&Bs[k][n4]) = v;
        }
        __syncthreads();

        #pragma unroll
        for (int k = 0; k < GBK; k++) {
            float4 a0 = *reinterpret_cast<float4*>(&As[k][ty * 8]);
            float4 a1 = *reinterpret_cast<float4*>(&As[k][ty * 8 + 4]);
            float4 b0 = *reinterpret_cast<float4*>(&Bs[k][tx * 4]);
            float4 b1 = *reinterpret_cast<float4*>(&Bs[k][64 + tx * 4]);
            float a[8] = {a0.x, a0.y, a0.z, a0.w, a1.x, a1.y, a1.z, a1.w};
            float b[8] = {b0.x, b0.y, b0.z, b0.w, b1.x, b1.y, b1.z, b1.w};
            #pragma unroll
            for (int i = 0; i < 8; i++)
                #pragma unroll
                for (int j = 0; j < 8; j++)
                    acc[i][j] = fmaf(a[i], b[j], acc[i][j]);
        }
        __syncthreads();
    }

    float4 bv0 = *reinterpret_cast<const float4*>(bias + tx * 4);
    float4 bv1 = *reinterpret_cast<const float4*>(bias + 64 + tx * 4);

    #pragma unroll
    for (int i = 0; i < 8; i++) {
        int gr = rowBase + ty * 8 + i;
        if (gr < N_NODES) {
            float4 o0, o1;
            o0.x = acc[i][0] + bv0.x; o0.y = acc[i][1] + bv0.y;
            o0.z = acc[i][2] + bv0.z; o0.w = acc[i][3] + bv0.w;
            o1.x = acc[i][4] + bv1.x; o1.y = acc[i][5] + bv1.y;
            o1.z = acc[i][6] + bv1.z; o1.w = acc[i][7] + bv1.w;
            float* p = out + (size_t)gr * D;
            *reinterpret_cast<float4*>(p + tx * 4) = o0;
            *reinterpret_cast<float4*>(p + 64 + tx * 4) = o1;
        }
    }
}

extern "C" void kernel_launch(void* const* d_in, const int* in_sizes, int n_in,
                              void* d_out, int out_size) {
    const float* input   = (const float*)d_in[0];
    const int*   adjrows = (const int*)d_in[1];   // jnp int64 -> int32 (x64 off)
    const int*   adjcols = (const int*)d_in[2];
    const float* adjvals = (const float*)d_in[3];
    const float* weight  = (const float*)d_in[4];
    const float* linw    = (const float*)d_in[5];
    const float* bias    = (const float*)d_in[6];

    float* out = (float*)d_out;  // [N_NODES, D]
    float* rep;
    if ((long long)out_size >= 2LL * N_NODES * D) {
        rep = out + (size_t)N_NODES * D;
    } else {
        cudaGetSymbolAddress((void**)&rep, g_rep);
    }

    // 1) fp16 table + zero counts
    prep_kernel<<<(N_NODES * D / 4 + 255) / 256, 256>>>((const float4*)input);

    // 2) bucketed edge fill (hist+fill fused, mix inline)
    fill_kernel<<<(TOTAL_E + 255) / 256, 256>>>(adjrows, adjcols, adjvals, linw);

    // 3) gather: one warp per row
    long long gthreads = (long long)N_NODES * 32;
    gather_kernel<<<(int)((gthreads + 255) / 256), 256>>>(input, linw, rep);

    // 4) dense projection
    gemm_kernel<<<(N_NODES + GBM - 1) / GBM, 256>>>(rep, weight, bias, out);
}

// round 14
// speedup vs baseline: 1.2908x; 1.2908x over previous
#include <cuda_runtime.h>
#include <cuda_fp16.h>

#define N_NODES 100000
#define D 128
#define N_ADJ 6
#define NNZ 600000
#define TOTAL_E (N_ADJ * NNZ)
#define N_HOPS 7

// multi-block scan geometry: 25 blocks x 1024 threads x 4 elems = 102400 >= 100000
#define SCAN_T 1024
#define SCAN_ELEMS (SCAN_T * 4)
#define SCAN_B ((N_NODES + SCAN_ELEMS - 1) / SCAN_ELEMS)

// ---------------- device scratch (static, no allocations) ----------------
__device__ float  g_mix[N_HOPS];
__device__ int    g_count[N_NODES];
__device__ int    g_offsets[N_NODES + 1];
__device__ int    g_cursor[N_NODES];
__device__ int    g_bsum[SCAN_B];
__device__ int    g_bpre[SCAN_B];
__device__ int2   g_edges[TOTAL_E];            // (col, weight-as-int) per edge, CSR order
__device__ __half g_inph[(size_t)N_NODES * D]; // fp16 copy of input for gather
__device__ float  g_rep[(size_t)N_NODES * D];  // fallback if d_out lacks rep slot

// ---------------- softmax of mixing weights ----------------
__global__ void mix_kernel(const float* __restrict__ lw) {
    if (threadIdx.x == 0) {
        float m = -1e30f;
        #pragma unroll
        for (int i = 0; i < N_HOPS; i++) m = fmaxf(m, lw[i]);
        float e[N_HOPS];
        float s = 0.f;
        #pragma unroll
        for (int i = 0; i < N_HOPS; i++) { e[i] = expf(lw[i] - m); s += e[i]; }
        float inv = 1.f / s;
        #pragma unroll
        for (int i = 0; i < N_HOPS; i++) g_mix[i] = e[i] * inv;
    }
}

// ---------------- fp32 -> fp16 copy of input ----------------
__global__ void tohalf_kernel(const float4* __restrict__ in) {
    int i = blockIdx.x * blockDim.x + threadIdx.x;  // over N*D/4
    if (i < N_NODES * D / 4) {
        float4 v = in[i];
        __half2 h0 = __floats2half2_rn(v.x, v.y);
        __half2 h1 = __floats2half2_rn(v.z, v.w);
        uint2 u;
        u.x = *reinterpret_cast<unsigned*>(&h0);
        u.y = *reinterpret_cast<unsigned*>(&h1);
        reinterpret_cast<uint2*>(g_inph)[i] = u;
    }
}

// ---------------- CSR build ----------------
__global__ void hist_kernel(const int* __restrict__ rows) {
    int e = blockIdx.x * blockDim.x + threadIdx.x;
    if (e < TOTAL_E) atomicAdd(&g_count[rows[e]], 1);
}

// pass 1: per-block totals
__global__ __launch_bounds__(SCAN_T) void scan_pass1() {
    __shared__ int warp_sums[32];
    int t = threadIdx.x;
    int lane = t & 31, wid = t >> 5;
    int idx = blockIdx.x * SCAN_ELEMS + t * 4;

    int local = 0;
    if (idx + 3 < N_NODES) {
        int4 c = *reinterpret_cast<const int4*>(g_count + idx);
        local = c.x + c.y + c.z + c.w;
    } else {
        for (int j = 0; j < 4; j++)
            if (idx + j < N_NODES) local += g_count[idx + j];
    }
    #pragma unroll
    for (int d = 16; d > 0; d >>= 1) local += __shfl_down_sync(0xffffffffu, local, d);
    if (lane == 0) warp_sums[wid] = local;
    __syncthreads();
    if (wid == 0) {
        int v = warp_sums[lane];
        #pragma unroll
        for (int d = 16; d > 0; d >>= 1) v += __shfl_down_sync(0xffffffffu, v, d);
        if (lane == 0) g_bsum[blockIdx.x] = v;
    }
}

// pass 2: exclusive scan of SCAN_B block sums (one warp)
__global__ void scan_pass2() {
    int lane = threadIdx.x;
    int v = (lane < SCAN_B) ? g_bsum[lane] : 0;
    int inc = v;
    #pragma unroll
    for (int d = 1; d < 32; d <<= 1) {
        int n = __shfl_up_sync(0xffffffffu, inc, d);
        if (lane >= d) inc += n;
    }
    if (lane < SCAN_B) g_bpre[lane] = inc - v;   // exclusive
    if (lane == 0) g_offsets[N_NODES] = TOTAL_E;
}

// pass 3: full scan within each block + block prefix -> offsets & cursors
__global__ __launch_bounds__(SCAN_T) void scan_pass3() {
    __shared__ int warp_sums[32];
    int t = threadIdx.x;
    int lane = t & 31, wid = t >> 5;
    int idx = blockIdx.x * SCAN_ELEMS + t * 4;

    int4 c = make_int4(0, 0, 0, 0);
    if (idx + 3 < N_NODES) {
        c = *reinterpret_cast<const int4*>(g_count + idx);
    } else {
        if (idx + 0 < N_NODES) c.x = g_count[idx + 0];
        if (idx + 1 < N_NODES) c.y = g_count[idx + 1];
        if (idx + 2 < N_NODES) c.z = g_count[idx + 2];
        if (idx + 3 < N_NODES) c.w = g_count[idx + 3];
    }
    int local = c.x + c.y + c.z + c.w;

    int v = local;
    #pragma unroll
    for (int d = 1; d < 32; d <<= 1) {
        int n = __shfl_up_sync(0xffffffffu, v, d);
        if (lane >= d) v += n;
    }
    if (lane == 31) warp_sums[wid] = v;
    __syncthreads();
    if (wid == 0) {
        int w = warp_sums[lane];
        #pragma unroll
        for (int d = 1; d < 32; d <<= 1) {
            int n = __shfl_up_sync(0xffffffffu, w, d);
            if (lane >= d) w += n;
        }
        warp_sums[lane] = w;
    }
    __syncthreads();

    int warp_prefix = (wid > 0) ? warp_sums[wid - 1] : 0;
    int excl = g_bpre[blockIdx.x] + warp_prefix + (v - local);
    int o0 = excl;
    int o1 = o0 + c.x;
    int o2 = o1 + c.y;
    int o3 = o2 + c.z;
    if (idx + 0 < N_NODES) { g_offsets[idx + 0] = o0; g_cursor[idx + 0] = o0; }
    if (idx + 1 < N_NODES) { g_offsets[idx + 1] = o1; g_cursor[idx + 1] = o1; }
    if (idx + 2 < N_NODES) { g_offsets[idx + 2] = o2; g_cursor[idx + 2] = o2; }
    if (idx + 3 < N_NODES) { g_offsets[idx + 3] = o3; g_cursor[idx + 3] = o3; }
}

__global__ void fill_kernel(const int* __restrict__ rows,
                            const int* __restrict__ cols,
                            const float* __restrict__ vals) {
    int e = blockIdx.x * blockDim.x + threadIdx.x;
    if (e >= TOTAL_E) return;
    int a = e / NNZ;
    int r = rows[e];
    int c = cols[e];
    float w = g_mix[a + 1] * vals[e];
    int slot = atomicAdd(&g_cursor[r], 1);
    g_edges[slot] = make_int2(c, __float_as_int(w));
}

// ---------------- gather: one warp per row; no shfl, uniform edge reads ----------------
// rep[r,:] = mix0*input_f32[r,:] + sum_{e in row r} w_e * input_f16[col_e,:]
__device__ __forceinline__ void gacc(float4& acc, float w, uint2 u) {
    __half2 h0 = *reinterpret_cast<__half2*>(&u.x);
    __half2 h1 = *reinterpret_cast<__half2*>(&u.y);
    float2 f0 = __half22float2(h0);
    float2 f1 = __half22float2(h1);
    acc.x = fmaf(w, f0.x, acc.x);
    acc.y = fmaf(w, f0.y, acc.y);
    acc.z = fmaf(w, f1.x, acc.z);
    acc.w = fmaf(w, f1.y, acc.w);
}

__global__ __launch_bounds__(256) void gather_kernel(const float* __restrict__ input,
                                                     float* __restrict__ rep) {
    int gw = (blockIdx.x * blockDim.x + threadIdx.x) >> 5;  // global warp = row
    int lane = threadIdx.x & 31;
    if (gw >= N_NODES) return;
    int row = gw;

    float m0 = g_mix[0];
    float4 acc = reinterpret_cast<const float4*>(input + (size_t)row * D)[lane];
    acc.x *= m0; acc.y *= m0; acc.z *= m0; acc.w *= m0;

    int beg = g_offsets[row];
    int end = g_offsets[row + 1];
    int e = beg;
    // 4x unrolled: 4 independent row-gathers in flight
    for (; e + 4 <= end; e += 4) {
        int2 e0 = __ldg(g_edges + e + 0);
        int2 e1 = __ldg(g_edges + e + 1);
        int2 e2 = __ldg(g_edges + e + 2);
        int2 e3 = __ldg(g_edges + e + 3);
        uint2 u0 = __ldg(reinterpret_cast<const uint2*>(g_inph + (size_t)e0.x * D) + lane);
        uint2 u1 = __ldg(reinterpret_cast<const uint2*>(g_inph + (size_t)e1.x * D) + lane);
        uint2 u2 = __ldg(reinterpret_cast<const uint2*>(g_inph + (size_t)e2.x * D) + lane);
        uint2 u3 = __ldg(reinterpret_cast<const uint2*>(g_inph + (size_t)e3.x * D) + lane);
        gacc(acc, __int_as_float(e0.y), u0);
        gacc(acc, __int_as_float(e1.y), u1);
        gacc(acc, __int_as_float(e2.y), u2);
        gacc(acc, __int_as_float(e3.y), u3);
    }
    for (; e < end; e++) {
        int2 ed = __ldg(g_edges + e);
        uint2 u = __ldg(reinterpret_cast<const uint2*>(g_inph + (size_t)ed.x * D) + lane);
        gacc(acc, __int_as_float(ed.y), u);
    }
    reinterpret_cast<float4*>(rep + (size_t)row * D)[lane] = acc;
}

// ---------------- out = rep @ W + bias  (R4 proven shape: 64x128 tile, 8x4 microtile) ----------------
#define BM 64
#define BK 16
__global__ __launch_bounds__(256) void gemm_kernel(const float* __restrict__ rep,
                                                   const float* __restrict__ W,
                                                   const float* __restrict__ bias,
                                                   float* __restrict__ out) {
    __shared__ float As[BK][BM + 4];
    __shared__ float Bs[BK][D];

    int tid = threadIdx.x;
    int tx = tid & 31;   // col group: cols [4*tx, 4*tx+4)
    int ty = tid >> 5;   // row group: rows [8*ty, 8*ty+8)
    int rowBase = blockIdx.x * BM;

    float acc[8][4];
    #pragma unroll
    for (int i = 0; i < 8; i++)
        #pragma unroll
        for (int j = 0; j < 4; j++) acc[i][j] = 0.f;

    for (int kk = 0; kk < D; kk += BK) {
        // Load A tile (64 x 16), one float4 per thread, transposed into As[k][r]
        {
            int r = tid >> 2;
            int c4 = (tid & 3) * 4;
            float4 v = make_float4(0.f, 0.f, 0.f, 0.f);
            int gr = rowBase + r;
            if (gr < N_NODES)
                v = *reinterpret_cast<const float4*>(rep + (size_t)gr * D + kk + c4);
            As[c4 + 0][r] = v.x;
            As[c4 + 1][r] = v.y;
            As[c4 + 2][r] = v.z;
            As[c4 + 3][r] = v.w;
        }
        // Load B tile (16 x 128), two float4 per thread
        #pragma unroll
        for (int j = 0; j < 2; j++) {
            int idx = tid + j * 256;
            int k = idx >> 5;
            int n4 = (idx & 31) * 4;
            float4 v = *reinterpret_cast<const float4*>(W + (size_t)(kk + k) * D + n4);
            *reinterpret_cast<float4*>(&Bs[k][n4]) = v;
        }
        __syncthreads();

        #pragma unroll
        for (int k = 0; k < BK; k++) {
            float a[8];
            #pragma unroll
            for (int i = 0; i < 8; i++) a[i] = As[k][ty * 8 + i];
            float4 b = *reinterpret_cast<float4*>(&Bs[k][tx * 4]);
            #pragma unroll
            for (int i = 0; i < 8; i++) {
                acc[i][0] = fmaf(a[i], b.x, acc[i][0]);
                acc[i][1] = fmaf(a[i], b.y, acc[i][1]);
                acc[i][2] = fmaf(a[i], b.z, acc[i][2]);
                acc[i][3] = fmaf(a[i], b.w, acc[i][3]);
            }
        }
        __syncthreads();
    }

    float4 bv = *reinterpret_cast<const float4*>(bias + tx * 4);
    #pragma unroll
    for (int i = 0; i < 8; i++) {
        int gr = rowBase + ty * 8 + i;
        if (gr < N_NODES) {
            float4 o;
            o.x = acc[i][0] + bv.x;
            o.y = acc[i][1] + bv.y;
            o.z = acc[i][2] + bv.z;
            o.w = acc[i][3] + bv.w;
            *reinterpret_cast<float4*>(out + (size_t)gr * D + tx * 4) = o;
        }
    }
}

extern "C" void kernel_launch(void* const* d_in, const int* in_sizes, int n_in,
                              void* d_out, int out_size) {
    const float* input   = (const float*)d_in[0];
    const int*   adjrows = (const int*)d_in[1];   // jnp int64 -> int32 (x64 off)
    const int*   adjcols = (const int*)d_in[2];
    const float* adjvals = (const float*)d_in[3];
    const float* weight  = (const float*)d_in[4];
    const float* linw    = (const float*)d_in[5];
    const float* bias    = (const float*)d_in[6];

    float* out = (float*)d_out;  // [N_NODES, D]
    float* rep;
    if ((long long)out_size >= 2LL * N_NODES * D) {
        rep = out + (size_t)N_NODES * D;
    } else {
        cudaGetSymbolAddress((void**)&rep, g_rep);
    }

    mix_kernel<<<1, 32>>>(linw);

    void* countPtr = nullptr;
    cudaGetSymbolAddress(&countPtr, g_count);
    cudaMemsetAsync(countPtr, 0, N_NODES * sizeof(int));

    tohalf_kernel<<<(N_NODES * D / 4 + 255) / 256, 256>>>((const float4*)input);

    hist_kernel<<<(TOTAL_E + 255) / 256, 256>>>(adjrows);
    scan_pass1<<<SCAN_B, SCAN_T>>>();
    scan_pass2<<<1, 32>>>();
    scan_pass3<<<SCAN_B, SCAN_T>>>();
    fill_kernel<<<(TOTAL_E + 255) / 256, 256>>>(adjrows, adjcols, adjvals);

    // one warp per row
    long long gthreads = (long long)N_NODES * 32;
    gather_kernel<<<(int)((gthreads + 255) / 256), 256>>>(input, rep);

    gemm_kernel<<<(N_NODES + BM - 1) / BM, 256>>>(rep, weight, bias, out);
}